// round 2
// baseline (speedup 1.0000x reference)
#include <cuda_runtime.h>
#include <cuda_bf16.h>
#include <mma.h>

using namespace nvcuda;

#define BATCH 4
#define C_DIM 512
#define N_Q   512
#define HW_T  76800
#define NTILE 128
#define MTILE 64
#define MS    9            // m-chunks per (batch, n-tile)
#define LDA   136          // 128 + 8 pad (bf16 elems), row = 272B (mult of 16)
#define LDB   72           // 64 + 8 pad
#define LDSCR 20           // fp32 scratch ld, row = 80B (mult of 16)

// exp factor: logits = dot * (100/512); exp(x) = exp2(x*log2e)
// K2 = (100/512) * 1.4426950408889634 = 0.2817763751
#define K2F 0.28177637515380313f

// smem layout (bytes)
#define OFF_A   0
#define SZ_A    (C_DIM * LDA * 2)              // 139264
#define OFF_B   (OFF_A + SZ_A)
#define SZ_B    (C_DIM * LDB * 2)              // 73728
#define OFF_SCR (OFF_B + SZ_B)                 // 212992
#define SZ_SCR  (8 * 16 * LDSCR * 4)           // 10240  (8 warps x 16x20 fp32)
#define OFF_CRD (OFF_SCR + SZ_SCR)             // 223232
#define SZ_CRD  (MTILE * 8)                    // 512 (float2 per m)
#define SMEM_TOTAL (OFF_CRD + SZ_CRD)          // 223744

// deterministic per-chunk partials: (sum_e, sum_e*x, sum_e*y, pad)
__device__ float4 g_partial[MS][BATCH][N_Q];

__global__ __launch_bounds__(256, 1)
void matcher_main(const float* __restrict__ src_desc,
                  const float* __restrict__ trg_desc,
                  const float* __restrict__ trg_xy)
{
    extern __shared__ __align__(16) char smem[];
    __nv_bfloat16* A_sh = (__nv_bfloat16*)(smem + OFF_A);
    __nv_bfloat16* B_sh = (__nv_bfloat16*)(smem + OFF_B);
    float*         scr  = (float*)(smem + OFF_SCR);
    float2*        crd  = (float2*)(smem + OFF_CRD);

    const int b     = blockIdx.z;
    const int nt    = blockIdx.y;
    const int chunk = blockIdx.x;
    const int tid   = threadIdx.x;
    const int w     = tid >> 5;
    const int lane  = tid & 31;
    const int n0    = nt * NTILE;

    // ---- Load A tile: src descriptors [c][n0..n0+127] -> bf16 smem, pre-scaled by K2 ----
    const float* Ag = src_desc + (size_t)b * C_DIM * N_Q + n0;
    for (int idx = tid; idx < C_DIM * (NTILE / 4); idx += 256) {
        int c = idx >> 5;          // NTILE/4 = 32 float4 per row
        int q = idx & 31;
        float4 v = *(const float4*)(Ag + (size_t)c * N_Q + 4 * q);
        __nv_bfloat162* dst = (__nv_bfloat162*)(A_sh + c * LDA + 4 * q);
        dst[0] = __floats2bfloat162_rn(v.x * K2F, v.y * K2F);
        dst[1] = __floats2bfloat162_rn(v.z * K2F, v.w * K2F);
    }
    __syncthreads();

    const int wn = w >> 1;   // 0..3 : warp's 32-row block within 128 n
    const int wm = w & 1;    // 0..1 : warp's 32-col block within 64 m

    float accE[2] = {0.f, 0.f};
    float accX[2] = {0.f, 0.f};
    float accY[2] = {0.f, 0.f};

    const int tiles = HW_T / MTILE;               // 1200
    const int t0 = (tiles * chunk) / MS;
    const int t1 = (tiles * (chunk + 1)) / MS;

    const float* Bg = trg_desc + (size_t)b * C_DIM * HW_T;
    const float* Xg = trg_xy + (size_t)b * 2 * HW_T;

    float* scr_w = scr + w * (16 * LDSCR);
    const int rl = lane & 15;
    const int cb = (lane >> 4) * 8;

    for (int t = t0; t < t1; ++t) {
        const int m0 = t * MTILE;

        // ---- Load B tile: trg descriptors [c][m0..m0+63] -> bf16 smem ----
        for (int idx = tid; idx < C_DIM * (MTILE / 4); idx += 256) {
            int c = idx >> 4;      // MTILE/4 = 16 float4 per row
            int q = idx & 15;
            float4 v = *(const float4*)(Bg + (size_t)c * HW_T + m0 + 4 * q);
            __nv_bfloat162* dst = (__nv_bfloat162*)(B_sh + c * LDB + 4 * q);
            dst[0] = __floats2bfloat162_rn(v.x, v.y);
            dst[1] = __floats2bfloat162_rn(v.z, v.w);
        }
        if (tid < MTILE) {
            crd[tid] = make_float2(Xg[m0 + tid], Xg[HW_T + m0 + tid]);
        }
        __syncthreads();

        // ---- S = A^T(128x512) * B(512x64), warp computes 32x32 ----
        wmma::fragment<wmma::accumulator, 16, 16, 16, float> acc[2][2];
        #pragma unroll
        for (int i = 0; i < 2; i++)
            #pragma unroll
            for (int j = 0; j < 2; j++)
                wmma::fill_fragment(acc[i][j], 0.f);

        #pragma unroll 4
        for (int k = 0; k < C_DIM; k += 16) {
            wmma::fragment<wmma::matrix_a, 16, 16, 16, __nv_bfloat16, wmma::col_major> a0, a1;
            wmma::fragment<wmma::matrix_b, 16, 16, 16, __nv_bfloat16, wmma::row_major> b0, b1;
            wmma::load_matrix_sync(a0, A_sh + k * LDA + 32 * wn, LDA);
            wmma::load_matrix_sync(a1, A_sh + k * LDA + 32 * wn + 16, LDA);
            wmma::load_matrix_sync(b0, B_sh + k * LDB + 32 * wm, LDB);
            wmma::load_matrix_sync(b1, B_sh + k * LDB + 32 * wm + 16, LDB);
            wmma::mma_sync(acc[0][0], a0, b0, acc[0][0]);
            wmma::mma_sync(acc[0][1], a0, b1, acc[0][1]);
            wmma::mma_sync(acc[1][0], a1, b0, acc[1][0]);
            wmma::mma_sync(acc[1][1], a1, b1, acc[1][1]);
        }

        // ---- Epilogue: exp + weighted coordinate accumulation (no max needed:
        //      |logit| <= ~0.2 since descriptors are unit-norm) ----
        #pragma unroll
        for (int fi = 0; fi < 2; fi++) {
            #pragma unroll
            for (int fj = 0; fj < 2; fj++) {
                wmma::store_matrix_sync(scr_w, acc[fi][fj], LDSCR, wmma::mem_row_major);
                __syncwarp();
                #pragma unroll
                for (int j = 0; j < 8; j++) {
                    float s = scr_w[rl * LDSCR + cb + j];   // already scaled by K2 via A
                    float e;
                    asm("ex2.approx.f32 %0, %1;" : "=f"(e) : "f"(s));
                    float2 xy = crd[32 * wm + 16 * fj + cb + j];
                    accE[fi] += e;
                    accX[fi] += e * xy.x;
                    accY[fi] += e * xy.y;
                }
                __syncwarp();
            }
        }
        __syncthreads();   // protect B_sh / crd for next iteration
    }

    // ---- Reduce: combine column halves (lanes l and l^16 share a row) ----
    #pragma unroll
    for (int fi = 0; fi < 2; fi++) {
        accE[fi] += __shfl_xor_sync(0xffffffffu, accE[fi], 16);
        accX[fi] += __shfl_xor_sync(0xffffffffu, accX[fi], 16);
        accY[fi] += __shfl_xor_sync(0xffffffffu, accY[fi], 16);
    }

    // Reuse A_sh space as the cross-warp (wm pair) reduction buffer.
    float4* red = (float4*)smem;            // [2][128]
    __syncthreads();
    if (lane < 16) {
        red[wm * NTILE + 32 * wn + lane]      = make_float4(accE[0], accX[0], accY[0], 0.f);
        red[wm * NTILE + 32 * wn + lane + 16] = make_float4(accE[1], accX[1], accY[1], 0.f);
    }
    __syncthreads();
    if (tid < NTILE) {
        float4 p0 = red[tid];
        float4 p1 = red[NTILE + tid];
        g_partial[chunk][b][n0 + tid] =
            make_float4(p0.x + p1.x, p0.y + p1.y, p0.z + p1.z, 0.f);
    }
}

__global__ void matcher_final(float* __restrict__ out)
{
    int idx = blockIdx.x * 256 + threadIdx.x;   // 0..2047
    if (idx >= BATCH * N_Q) return;
    int b = idx >> 9;
    int n = idx & (N_Q - 1);
    float e = 0.f, x = 0.f, y = 0.f;
    #pragma unroll
    for (int c = 0; c < MS; c++) {
        float4 p = g_partial[c][b][n];
        e += p.x; x += p.y; y += p.z;
    }
    out[(size_t)b * 2 * N_Q + n]        = x / e;
    out[(size_t)b * 2 * N_Q + N_Q + n]  = y / e;
}

extern "C" void kernel_launch(void* const* d_in, const int* in_sizes, int n_in,
                              void* d_out, int out_size)
{
    // metadata order: kpt_2D_src, kpt_2D_trg, kpt_desc_norm_src, kpt_desc_norm_trg
    const float* kpt_trg = (const float*)d_in[1];
    const float* dsrc    = (const float*)d_in[2];
    const float* dtrg    = (const float*)d_in[3];

    cudaFuncSetAttribute(matcher_main,
                         cudaFuncAttributeMaxDynamicSharedMemorySize, SMEM_TOTAL);

    dim3 grid(MS, N_Q / NTILE, BATCH);          // 9 x 4 x 4 = 144 CTAs (one wave)
    matcher_main<<<grid, 256, SMEM_TOTAL>>>(dsrc, dtrg, kpt_trg);
    matcher_final<<<(BATCH * N_Q + 255) / 256, 256>>>((float*)d_out);
}

// round 3
// speedup vs baseline: 1.0055x; 1.0055x over previous
#include <cuda_runtime.h>
#include <cuda_bf16.h>
#include <mma.h>

using namespace nvcuda;

#define BATCH 4
#define C_DIM 512
#define N_Q   512
#define HW_T  76800
#define NTILE 128
#define MTILE 64
#define MS    9            // m-chunks per (batch, n-tile)
#define LDA   136          // 128 + 8 pad (bf16 elems), row = 272B (mult of 16)
#define LDB   72           // 64 + 8 pad
#define LDSCR 20           // fp32 scratch ld, row = 80B (mult of 16)

// exp factor: logits = dot * (100/512); exp(x) = exp2(x*log2e)
// K2 = (100/512) * 1.4426950408889634 = 0.2817763751
#define K2F 0.28177637515380313f

// smem layout (bytes)
#define OFF_A   0
#define SZ_A    (C_DIM * LDA * 2)              // 139264
#define OFF_B   (OFF_A + SZ_A)
#define SZ_B    (C_DIM * LDB * 2)              // 73728
#define OFF_SCR (OFF_B + SZ_B)                 // 212992
#define SZ_SCR  (8 * 16 * LDSCR * 4)           // 10240  (8 warps x 16x20 fp32)
#define OFF_CRD (OFF_SCR + SZ_SCR)             // 223232
#define SZ_CRD  (MTILE * 8)                    // 512 (float2 per m)
#define SMEM_TOTAL (OFF_CRD + SZ_CRD)          // 223744

// deterministic per-chunk partials: (sum_e, sum_e*x, sum_e*y, pad)
__device__ float4 g_partial[MS][BATCH][N_Q];

// exp2(s) for |s| <= ~0.30 : degree-4 Taylor in ln2, rel err ~3e-6.
// Keeps the epilogue entirely on the FMA pipe (MUFU rt=8 was the R1 bottleneck).
__device__ __forceinline__ float exp2_poly(float s) {
    const float c1 = 0.69314718056f;
    const float c2 = 0.24022650700f;
    const float c3 = 0.05550410866f;
    const float c4 = 0.00961812911f;
    float p = fmaf(s, c4, c3);
    p = fmaf(s, p, c2);
    p = fmaf(s, p, c1);
    return fmaf(s, p, 1.0f);
}

__global__ __launch_bounds__(256, 1)
void matcher_main(const float* __restrict__ src_desc,
                  const float* __restrict__ trg_desc,
                  const float* __restrict__ trg_xy)
{
    extern __shared__ __align__(16) char smem[];
    __nv_bfloat16* A_sh = (__nv_bfloat16*)(smem + OFF_A);
    __nv_bfloat16* B_sh = (__nv_bfloat16*)(smem + OFF_B);
    float*         scr  = (float*)(smem + OFF_SCR);
    float2*        crd  = (float2*)(smem + OFF_CRD);

    const int b     = blockIdx.z;
    const int nt    = blockIdx.y;
    const int chunk = blockIdx.x;
    const int tid   = threadIdx.x;
    const int w     = tid >> 5;
    const int lane  = tid & 31;
    const int n0    = nt * NTILE;

    // ---- Load A tile: src descriptors [c][n0..n0+127] -> bf16 smem, pre-scaled by K2 ----
    const float* Ag = src_desc + (size_t)b * C_DIM * N_Q + n0;
    for (int idx = tid; idx < C_DIM * (NTILE / 4); idx += 256) {
        int c = idx >> 5;          // NTILE/4 = 32 float4 per row
        int q = idx & 31;
        float4 v = *(const float4*)(Ag + (size_t)c * N_Q + 4 * q);
        __nv_bfloat162* dst = (__nv_bfloat162*)(A_sh + c * LDA + 4 * q);
        dst[0] = __floats2bfloat162_rn(v.x * K2F, v.y * K2F);
        dst[1] = __floats2bfloat162_rn(v.z * K2F, v.w * K2F);
    }
    __syncthreads();

    const int wn = w >> 1;   // 0..3 : warp's 32-row block within 128 n
    const int wm = w & 1;    // 0..1 : warp's 32-col block within 64 m

    float accE[2] = {0.f, 0.f};
    float accX[2] = {0.f, 0.f};
    float accY[2] = {0.f, 0.f};

    const int tiles = HW_T / MTILE;               // 1200
    const int t0 = (tiles * chunk) / MS;
    const int t1 = (tiles * (chunk + 1)) / MS;

    const float* Bg = trg_desc + (size_t)b * C_DIM * HW_T;
    const float* Xg = trg_xy + (size_t)b * 2 * HW_T;

    float* scr_w = scr + w * (16 * LDSCR);
    const int rl = lane & 15;
    const int cb = (lane >> 4) * 8;

    for (int t = t0; t < t1; ++t) {
        const int m0 = t * MTILE;

        // ---- Load B tile: trg descriptors [c][m0..m0+63] -> bf16 smem ----
        for (int idx = tid; idx < C_DIM * (MTILE / 4); idx += 256) {
            int c = idx >> 4;      // MTILE/4 = 16 float4 per row
            int q = idx & 15;
            float4 v = *(const float4*)(Bg + (size_t)c * HW_T + m0 + 4 * q);
            __nv_bfloat162* dst = (__nv_bfloat162*)(B_sh + c * LDB + 4 * q);
            dst[0] = __floats2bfloat162_rn(v.x, v.y);
            dst[1] = __floats2bfloat162_rn(v.z, v.w);
        }
        if (tid < MTILE) {
            crd[tid] = make_float2(Xg[m0 + tid], Xg[HW_T + m0 + tid]);
        }
        __syncthreads();

        // ---- S = A^T(128x512) * B(512x64), warp computes 32x32 ----
        wmma::fragment<wmma::accumulator, 16, 16, 16, float> acc[2][2];
        #pragma unroll
        for (int i = 0; i < 2; i++)
            #pragma unroll
            for (int j = 0; j < 2; j++)
                wmma::fill_fragment(acc[i][j], 0.f);

        #pragma unroll 4
        for (int k = 0; k < C_DIM; k += 16) {
            wmma::fragment<wmma::matrix_a, 16, 16, 16, __nv_bfloat16, wmma::col_major> a0, a1;
            wmma::fragment<wmma::matrix_b, 16, 16, 16, __nv_bfloat16, wmma::row_major> b0, b1;
            wmma::load_matrix_sync(a0, A_sh + k * LDA + 32 * wn, LDA);
            wmma::load_matrix_sync(a1, A_sh + k * LDA + 32 * wn + 16, LDA);
            wmma::load_matrix_sync(b0, B_sh + k * LDB + 32 * wm, LDB);
            wmma::load_matrix_sync(b1, B_sh + k * LDB + 32 * wm + 16, LDB);
            wmma::mma_sync(acc[0][0], a0, b0, acc[0][0]);
            wmma::mma_sync(acc[0][1], a0, b1, acc[0][1]);
            wmma::mma_sync(acc[1][0], a1, b0, acc[1][0]);
            wmma::mma_sync(acc[1][1], a1, b1, acc[1][1]);
        }

        // ---- Epilogue: polynomial exp2 + weighted coordinate accumulation.
        //      |logit_log2| <= ~0.29 (unit-norm descriptors) -> no max pass,
        //      and a deg-4 Taylor for 2^s is accurate to ~3e-6 — FMA pipe only. ----
        #pragma unroll
        for (int fi = 0; fi < 2; fi++) {
            #pragma unroll
            for (int fj = 0; fj < 2; fj++) {
                wmma::store_matrix_sync(scr_w, acc[fi][fj], LDSCR, wmma::mem_row_major);
                __syncwarp();
                #pragma unroll
                for (int j = 0; j < 8; j++) {
                    float s = scr_w[rl * LDSCR + cb + j];   // already scaled by K2 via A
                    float2 xy = crd[32 * wm + 16 * fj + cb + j];
                    float e = exp2_poly(s);
                    accE[fi] += e;
                    accX[fi] = fmaf(e, xy.x, accX[fi]);
                    accY[fi] = fmaf(e, xy.y, accY[fi]);
                }
                __syncwarp();
            }
        }
        __syncthreads();   // protect B_sh / crd for next iteration
    }

    // ---- Reduce: combine column halves (lanes l and l^16 share a row) ----
    #pragma unroll
    for (int fi = 0; fi < 2; fi++) {
        accE[fi] += __shfl_xor_sync(0xffffffffu, accE[fi], 16);
        accX[fi] += __shfl_xor_sync(0xffffffffu, accX[fi], 16);
        accY[fi] += __shfl_xor_sync(0xffffffffu, accY[fi], 16);
    }

    // Reuse A_sh space as the cross-warp (wm pair) reduction buffer.
    float4* red = (float4*)smem;            // [2][128]
    __syncthreads();
    if (lane < 16) {
        red[wm * NTILE + 32 * wn + lane]      = make_float4(accE[0], accX[0], accY[0], 0.f);
        red[wm * NTILE + 32 * wn + lane + 16] = make_float4(accE[1], accX[1], accY[1], 0.f);
    }
    __syncthreads();
    if (tid < NTILE) {
        float4 p0 = red[tid];
        float4 p1 = red[NTILE + tid];
        g_partial[chunk][b][n0 + tid] =
            make_float4(p0.x + p1.x, p0.y + p1.y, p0.z + p1.z, 0.f);
    }
}

__global__ void matcher_final(float* __restrict__ out)
{
    int idx = blockIdx.x * 256 + threadIdx.x;   // 0..2047
    if (idx >= BATCH * N_Q) return;
    int b = idx >> 9;
    int n = idx & (N_Q - 1);
    float e = 0.f, x = 0.f, y = 0.f;
    #pragma unroll
    for (int c = 0; c < MS; c++) {
        float4 p = g_partial[c][b][n];
        e += p.x; x += p.y; y += p.z;
    }
    out[(size_t)b * 2 * N_Q + n]        = x / e;
    out[(size_t)b * 2 * N_Q + N_Q + n]  = y / e;
}

extern "C" void kernel_launch(void* const* d_in, const int* in_sizes, int n_in,
                              void* d_out, int out_size)
{
    // metadata order: kpt_2D_src, kpt_2D_trg, kpt_desc_norm_src, kpt_desc_norm_trg
    const float* kpt_trg = (const float*)d_in[1];
    const float* dsrc    = (const float*)d_in[2];
    const float* dtrg    = (const float*)d_in[3];

    cudaFuncSetAttribute(matcher_main,
                         cudaFuncAttributeMaxDynamicSharedMemorySize, SMEM_TOTAL);

    dim3 grid(MS, N_Q / NTILE, BATCH);          // 9 x 4 x 4 = 144 CTAs (one wave)
    matcher_main<<<grid, 256, SMEM_TOTAL>>>(dsrc, dtrg, kpt_trg);
    matcher_final<<<(BATCH * N_Q + 255) / 256, 256>>>((float*)d_out);
}

// round 5
// speedup vs baseline: 1.0280x; 1.0223x over previous
#include <cuda_runtime.h>
#include <cuda_bf16.h>
#include <cstdint>

// ==================== problem constants ====================
#define BATCH 4
#define C_DIM 512
#define N_Q   512
#define HW_T  76800
#define NTILE 128          // keypoints per CTA (MMA M)
#define MT    64           // hw points per tile (MMA N)
#define MS    9            // m-chunks per (batch, n-tile)
// logits = dot * (100/512); exp(x) = 2^(x*log2e): K2 = (100/512)*log2(e)
#define K2F   0.28177637515380313f

// ==================== smem layout (bytes) ====================
// A: [128 kp][512 ch] bf16, row = 1024B, per-row XOR swizzle on 16B chunks
// B: 2 slots, each [256 ch][64 m] bf16, row = 128B, SW128-style swizzle
// crd: 2 x 64 float2
#define OFF_A    0
#define SZ_A     (128 * 1024)            // 131072
#define OFF_B    SZ_A
#define SZ_BSLOT (256 * 128)             // 32768
#define OFF_CRD  (OFF_B + 2 * SZ_BSLOT)  // 196608
#define SZ_CRD   (2 * 64 * 8)            // 1024
#define SMEM_TOTAL (OFF_CRD + SZ_CRD)    // 197632

// deterministic per-chunk partials: (sum_e, sum_e*x, sum_e*y, pad)
__device__ float4 g_partial[MS][BATCH][N_Q];

// ==================== PTX helpers (family-level, compute_103-safe) ====================
__device__ __forceinline__ uint32_t smem_u32(const void* p) {
    uint32_t a;
    asm("{ .reg .u64 t; cvta.to.shared.u64 t, %1; cvt.u32.u64 %0, t; }"
        : "=r"(a) : "l"(p));
    return a;
}

__device__ __forceinline__ void ldsm_x4(uint32_t& r0, uint32_t& r1,
                                        uint32_t& r2, uint32_t& r3, uint32_t addr) {
    asm volatile("ldmatrix.sync.aligned.m8n8.x4.shared.b16 {%0,%1,%2,%3}, [%4];"
        : "=r"(r0), "=r"(r1), "=r"(r2), "=r"(r3) : "r"(addr));
}
__device__ __forceinline__ void ldsm_x4_t(uint32_t& r0, uint32_t& r1,
                                          uint32_t& r2, uint32_t& r3, uint32_t addr) {
    asm volatile("ldmatrix.sync.aligned.m8n8.x4.trans.shared.b16 {%0,%1,%2,%3}, [%4];"
        : "=r"(r0), "=r"(r1), "=r"(r2), "=r"(r3) : "r"(addr));
}
__device__ __forceinline__ void mma_bf16(float* d, uint32_t a0, uint32_t a1,
                                         uint32_t a2, uint32_t a3,
                                         uint32_t b0, uint32_t b1) {
    asm volatile(
        "mma.sync.aligned.m16n8k16.row.col.f32.bf16.bf16.f32 "
        "{%0,%1,%2,%3}, {%4,%5,%6,%7}, {%8,%9}, {%0,%1,%2,%3};"
        : "+f"(d[0]), "+f"(d[1]), "+f"(d[2]), "+f"(d[3])
        : "r"(a0), "r"(a1), "r"(a2), "r"(a3), "r"(b0), "r"(b1));
}

#define BAR1() asm volatile("bar.sync 1, 256;" ::: "memory")
#define BAR2() asm volatile("bar.sync 2, 256;" ::: "memory")

// 2^s for |s| <= ~0.30 : degree-4 Taylor in ln2, rel err ~3e-6. FMA pipe only.
__device__ __forceinline__ float exp2_poly(float s) {
    const float c1 = 0.69314718056f;
    const float c2 = 0.24022650700f;
    const float c3 = 0.05550410866f;
    const float c4 = 0.00961812911f;
    float p = fmaf(s, c4, c3);
    p = fmaf(s, p, c2);
    p = fmaf(s, p, c1);
    return fmaf(s, p, 1.0f);
}

__device__ __forceinline__ uint32_t pack_bf2(float x, float y) {
    __nv_bfloat162 h = __floats2bfloat162_rn(x, y);
    return *reinterpret_cast<uint32_t*>(&h);
}

// ==================== producer fill: one half-tile (256 ch x 64 m) ====================
__device__ __forceinline__ void fill_slot(const float* __restrict__ Bg,
                                          char* smem, int slot, int chbase,
                                          int m0, int tidp)
{
    char* S = smem + OFF_B + slot * SZ_BSLOT;
    #pragma unroll 4
    for (int i = 0; i < 32; ++i) {
        int idx = tidp + i * 128;
        int m4 = idx & 15;          // 16B group along m (4 fp32)
        int kl = idx >> 4;          // local ch row 0..255
        const float4 v = *(const float4*)(Bg + (size_t)(chbase + kl) * HW_T + m0 + m4 * 4);
        uint2 pk;
        pk.x = pack_bf2(v.x, v.y);
        pk.y = pack_bf2(v.z, v.w);
        int chunk = m4 >> 1;        // 16B chunk along m (0..7)
        int off = kl * 128 + (((chunk) ^ (kl & 7)) << 4) + (m4 & 1) * 8;
        *(uint2*)(S + off) = pk;
    }
}

// ==================== main kernel ====================
__global__ __launch_bounds__(256, 1)
void matcher_mma(const float* __restrict__ src_desc,
                 const float* __restrict__ trg_desc,
                 const float* __restrict__ trg_xy)
{
    extern __shared__ __align__(1024) char smem[];
    const uint32_t sb = smem_u32(smem);

    const int b     = blockIdx.z;
    const int nt    = blockIdx.y;
    const int chunk = blockIdx.x;
    const int tid   = threadIdx.x;
    const int w     = tid >> 5;
    const int lane  = tid & 31;
    const int n0    = nt * NTILE;

    // ---- A prolog (all 256 threads): src[ch][kp] fp32 -> smem [kp][ch] bf16 * K2 ----
    {
        const float* Ag = src_desc + (size_t)b * C_DIM * N_Q + n0;
        #pragma unroll 4
        for (int i = 0; i < 32; ++i) {
            int idx = tid + i * 256;
            int kp4 = idx & 31;          // 4-keypoint group
            int chp = idx >> 5;          // ch-pair 0..255
            const float* p = Ag + (size_t)(2 * chp) * N_Q + kp4 * 4;
            float4 v0 = *(const float4*)p;
            float4 v1 = *(const float4*)(p + N_Q);
            const float* a0 = &v0.x;
            const float* a1 = &v1.x;
            int chunkA = chp >> 2;                // 16B chunk = 8 ch
            int within = (chp & 3) * 4;
            #pragma unroll
            for (int j = 0; j < 4; ++j) {
                int n = kp4 * 4 + j;
                uint32_t pk = pack_bf2(a0[j] * K2F, a1[j] * K2F);
                int off = n * 1024 + ((chunkA ^ (n & 7)) << 4) + within;
                *(uint32_t*)(smem + off) = pk;
            }
        }
    }
    __syncthreads();

    const int tiles = HW_T / MT;                 // 1200
    const int t0 = (tiles * chunk) / MS;
    const int T  = (tiles * (chunk + 1)) / MS - t0;

    const float* Bg = trg_desc + (size_t)b * C_DIM * HW_T;
    const float* Xg = trg_xy   + (size_t)b * 2 * HW_T;

    if (w >= 4) {
        // =============== producer: warps 4-7 ===============
        const int tidp = tid - 128;
        for (int t = 0; t < T; ++t) {
            const int m0 = (t0 + t) * MT;
            // half 0 -> slot 0 (+ coords for this tile)
            fill_slot(Bg, smem, 0, 0, m0, tidp);
            if (tidp < MT) {
                float2* crd = (float2*)(smem + OFF_CRD) + (t & 1) * MT;
                crd[tidp] = make_float2(Xg[m0 + tidp], Xg[HW_T + m0 + tidp]);
            }
            BAR1();
            // half 1 -> slot 1
            fill_slot(Bg, smem, 1, 256, m0, tidp);
            BAR2();
        }
    } else {
        // =============== consumer: warps 0-3 ===============
        // Per-lane ldmatrix address bases.
        const int rowA = lane & 15;
        const int hi   = lane >> 4;
        const int xorA = rowA & 7;
        const uint32_t baseA0 = sb + OFF_A + (uint32_t)(32 * w + rowA) * 1024u;
        const uint32_t baseA1 = baseA0 + 16 * 1024u;
        // B: row = 16*ks + rowB ; swizzle xor = rowB&7 (ks*16 keeps low 3 bits)
        const int rowB = lane & 15;
        const int xorB = rowB & 7;
        uint32_t baseB[4];
        #pragma unroll
        for (int g = 0; g < 4; ++g)
            baseB[g] = sb + OFF_B + (uint32_t)rowB * 128u
                     + (uint32_t)(((2 * g + hi) ^ xorB) << 4);

        float accE[2][2] = {{0.f,0.f},{0.f,0.f}};
        float accX[2][2] = {{0.f,0.f},{0.f,0.f}};
        float accY[2][2] = {{0.f,0.f},{0.f,0.f}};

        for (int t = 0; t < T; ++t) {
            float d[2][8][4];
            #pragma unroll
            for (int mf = 0; mf < 2; ++mf)
                #pragma unroll
                for (int nf = 0; nf < 8; ++nf)
                    #pragma unroll
                    for (int r = 0; r < 4; ++r)
                        d[mf][nf][r] = 0.f;

            #pragma unroll 1
            for (int h = 0; h < 2; ++h) {
                if (h == 0) BAR1(); else BAR2();
                const uint32_t slotOfs = (uint32_t)h * SZ_BSLOT;
                const int cbase = h * 32;       // A 16B-chunk base for this half
                #pragma unroll 4
                for (int ks = 0; ks < 16; ++ks) {
                    const uint32_t chA = (uint32_t)(((cbase + 2 * ks + hi) ^ xorA) << 4);
                    uint32_t a0,a1,a2,a3, a4,a5,a6,a7;
                    ldsm_x4(a0,a1,a2,a3, baseA0 + chA);
                    ldsm_x4(a4,a5,a6,a7, baseA1 + chA);
                    uint32_t br[4][4];
                    const uint32_t ko = slotOfs + (uint32_t)ks * 2048u;
                    #pragma unroll
                    for (int g = 0; g < 4; ++g)
                        ldsm_x4_t(br[g][0], br[g][1], br[g][2], br[g][3], baseB[g] + ko);
                    #pragma unroll
                    for (int g = 0; g < 4; ++g) {
                        mma_bf16(d[0][2*g],   a0,a1,a2,a3, br[g][0], br[g][1]);
                        mma_bf16(d[0][2*g+1], a0,a1,a2,a3, br[g][2], br[g][3]);
                        mma_bf16(d[1][2*g],   a4,a5,a6,a7, br[g][0], br[g][1]);
                        mma_bf16(d[1][2*g+1], a4,a5,a6,a7, br[g][2], br[g][3]);
                    }
                }
            }

            // ---- register epilogue: exp + weighted coordinate accumulation ----
            const float2* crd = (const float2*)(smem + OFF_CRD) + (t & 1) * MT;
            const int c0i = 2 * (lane & 3);
            #pragma unroll
            for (int nf = 0; nf < 8; ++nf) {
                float2 c0 = crd[8 * nf + c0i];
                float2 c1 = crd[8 * nf + c0i + 1];
                #pragma unroll
                for (int mf = 0; mf < 2; ++mf) {
                    float e0 = exp2_poly(d[mf][nf][0]);   // row l>>2,    col c0
                    float e1 = exp2_poly(d[mf][nf][1]);   // row l>>2,    col c1
                    float e2 = exp2_poly(d[mf][nf][2]);   // row l>>2+8,  col c0
                    float e3 = exp2_poly(d[mf][nf][3]);   // row l>>2+8,  col c1
                    accE[mf][0] += e0 + e1;
                    accE[mf][1] += e2 + e3;
                    accX[mf][0] = fmaf(e0, c0.x, fmaf(e1, c1.x, accX[mf][0]));
                    accY[mf][0] = fmaf(e0, c0.y, fmaf(e1, c1.y, accY[mf][0]));
                    accX[mf][1] = fmaf(e2, c0.x, fmaf(e3, c1.x, accX[mf][1]));
                    accY[mf][1] = fmaf(e2, c0.y, fmaf(e3, c1.y, accY[mf][1]));
                }
            }
        }

        // ---- final: reduce over the 4 lanes sharing each row, then store ----
        #pragma unroll
        for (int mf = 0; mf < 2; ++mf) {
            #pragma unroll
            for (int rh = 0; rh < 2; ++rh) {
                float e = accE[mf][rh], x = accX[mf][rh], y = accY[mf][rh];
                e += __shfl_xor_sync(0xffffffffu, e, 1);
                e += __shfl_xor_sync(0xffffffffu, e, 2);
                x += __shfl_xor_sync(0xffffffffu, x, 1);
                x += __shfl_xor_sync(0xffffffffu, x, 2);
                y += __shfl_xor_sync(0xffffffffu, y, 1);
                y += __shfl_xor_sync(0xffffffffu, y, 2);
                if ((lane & 3) == 0) {
                    int row = 32 * w + 16 * mf + 8 * rh + (lane >> 2);
                    g_partial[chunk][b][n0 + row] = make_float4(e, x, y, 0.f);
                }
            }
        }
    }
}

// ==================== finalize ====================
__global__ void matcher_final(float* __restrict__ out)
{
    int idx = blockIdx.x * 256 + threadIdx.x;   // 0..2047
    if (idx >= BATCH * N_Q) return;
    int b = idx >> 9;
    int n = idx & (N_Q - 1);
    float e = 0.f, x = 0.f, y = 0.f;
    #pragma unroll
    for (int c = 0; c < MS; c++) {
        float4 p = g_partial[c][b][n];
        e += p.x; x += p.y; y += p.z;
    }
    out[(size_t)b * 2 * N_Q + n]       = x / e;
    out[(size_t)b * 2 * N_Q + N_Q + n] = y / e;
}

// ==================== launch ====================
extern "C" void kernel_launch(void* const* d_in, const int* in_sizes, int n_in,
                              void* d_out, int out_size)
{
    // metadata order: kpt_2D_src, kpt_2D_trg, kpt_desc_norm_src, kpt_desc_norm_trg
    const float* kpt_trg = (const float*)d_in[1];
    const float* dsrc    = (const float*)d_in[2];
    const float* dtrg    = (const float*)d_in[3];

    cudaFuncSetAttribute(matcher_mma,
                         cudaFuncAttributeMaxDynamicSharedMemorySize, SMEM_TOTAL);

    dim3 grid(MS, N_Q / NTILE, BATCH);          // 9 x 4 x 4 = 144 CTAs (one wave)
    matcher_mma<<<grid, 256, SMEM_TOTAL>>>(dsrc, dtrg, kpt_trg);
    matcher_final<<<(BATCH * N_Q + 255) / 256, 256>>>((float*)d_out);
}